// round 8
// baseline (speedup 1.0000x reference)
#include <cuda_runtime.h>
#include <math.h>

#define N_NODES 100000
#define N_EDGES 1600000
#define HID 64
#define CAP 96              // max degree bucket capacity (Poisson(16) tail << 96)

// Scratch (no cudaMalloc allowed).
__device__ float g_h[N_NODES * HID];            // 25.6 MB
__device__ float g_dotu[N_NODES];
__device__ float g_dotv[N_NODES];
__device__ int   g_cnt[N_NODES];
__device__ int2  g_bucket[N_NODES * CAP];       // 76.8 MB: (src, w_bits) per edge

// ---------------------------------------------------------------------------
// f32x2 helpers (packed dual-fp32 FMA).
// ---------------------------------------------------------------------------
__device__ __forceinline__ unsigned long long pack2(float x, float y) {
    unsigned long long r;
    asm("mov.b64 %0, {%1, %2};" : "=l"(r) : "f"(x), "f"(y));
    return r;
}
__device__ __forceinline__ void unpack2(unsigned long long v, float& x, float& y) {
    asm("mov.b64 {%0, %1}, %2;" : "=f"(x), "=f"(y) : "l"(v));
}
__device__ __forceinline__ void fma2(unsigned long long& acc,
                                     unsigned long long a,
                                     unsigned long long b) {
    asm("fma.rn.f32x2 %0, %1, %2, %0;" : "+l"(acc) : "l"(a), "l"(b));
}

// ---------------------------------------------------------------------------
// K0: zero per-node counters.
// ---------------------------------------------------------------------------
__global__ void zero_kernel() {
    int i = blockIdx.x * blockDim.x + threadIdx.x;
    if (i < N_NODES) g_cnt[i] = 0;
}

// ---------------------------------------------------------------------------
// K1: h = feat @ W_in + b_in (f32x2 FFMA2), fused gate dot products.
// ---------------------------------------------------------------------------
__global__ void input_gemm_kernel(const float* __restrict__ feat,
                                  const float* __restrict__ W_in,
                                  const float* __restrict__ b_in,
                                  const float* __restrict__ W_edge) {
    __shared__ __align__(16) float sW[HID * HID];
    __shared__ float sB[HID];
    __shared__ float sT[HID][HID + 1];
    __shared__ float sWu[HID], sWv[HID];

    int tid   = threadIdx.x;
    int node0 = blockIdx.x * 64;
    int n     = tid & 63;
    int q     = tid >> 6;

    for (int k = tid; k < HID * HID; k += 256) sW[k] = W_in[k];
    if (tid < HID) {
        sB[tid]  = b_in[tid];
        sWu[tid] = W_edge[tid];
        sWv[tid] = W_edge[HID + tid];
    }
    for (int idx = tid; idx < 64 * HID; idx += 256) {
        int nn = idx >> 6, k = idx & 63;
        int gn = node0 + nn;
        sT[k][nn] = (gn < N_NODES) ? feat[gn * HID + k] : 0.0f;
    }
    __syncthreads();

    unsigned long long acc[8];
    {
        int j0 = q * 16;
#pragma unroll
        for (int p = 0; p < 8; p++) acc[p] = pack2(sB[j0 + 2 * p], sB[j0 + 2 * p + 1]);
    }
    const ulonglong2* sW2 = (const ulonglong2*)sW;
#pragma unroll 8
    for (int k = 0; k < HID; k++) {
        float f = sT[k][n];
        unsigned long long ff = pack2(f, f);
        ulonglong2 wA = sW2[k * 16 + q * 4 + 0];
        ulonglong2 wB = sW2[k * 16 + q * 4 + 1];
        ulonglong2 wC = sW2[k * 16 + q * 4 + 2];
        ulonglong2 wD = sW2[k * 16 + q * 4 + 3];
        fma2(acc[0], ff, wA.x); fma2(acc[1], ff, wA.y);
        fma2(acc[2], ff, wB.x); fma2(acc[3], ff, wB.y);
        fma2(acc[4], ff, wC.x); fma2(acc[5], ff, wC.y);
        fma2(acc[6], ff, wD.x); fma2(acc[7], ff, wD.y);
    }
    __syncthreads();

    {
        int j0 = q * 16;
#pragma unroll
        for (int p = 0; p < 8; p++) {
            float x, y;
            unpack2(acc[p], x, y);
            sT[j0 + 2 * p][n]     = x;
            sT[j0 + 2 * p + 1][n] = y;
        }
    }
    __syncthreads();

    for (int idx = tid; idx < 64 * HID; idx += 256) {
        int nn = idx >> 6, j = idx & 63;
        int gn = node0 + nn;
        if (gn < N_NODES) g_h[gn * HID + j] = sT[j][nn];
    }
    if (tid < 64) {
        int gn = node0 + tid;
        if (gn < N_NODES) {
            float du = 0.f, dv = 0.f;
#pragma unroll
            for (int j = 0; j < HID; j++) {
                float hv = sT[j][tid];
                du = fmaf(hv, sWu[j], du);
                dv = fmaf(hv, sWv[j], dv);
            }
            g_dotu[gn] = du;
            g_dotv[gn] = dv;
        }
    }
}

// ---------------------------------------------------------------------------
// K2: bucket scatter WITH fused gate. Runs after GEMM. 4 edges per thread.
// Stores (src, sigmoid(dotu[src]+dotv[dst]+b)) into dst's bucket.
// ---------------------------------------------------------------------------
__global__ void scatter_kernel(const int* __restrict__ src,
                               const int* __restrict__ dst,
                               const float* __restrict__ b_edge) {
    int t = blockIdx.x * blockDim.x + threadIdx.x;
    if (t * 4 >= N_EDGES) return;
    int4 s = ((const int4*)src)[t];
    int4 d = ((const int4*)dst)[t];
    float be = b_edge[0];

    // issue all random loads first (MLP 8)
    float dux = g_dotu[s.x], duy = g_dotu[s.y], duz = g_dotu[s.z], duw = g_dotu[s.w];
    float dvx = g_dotv[d.x], dvy = g_dotv[d.y], dvz = g_dotv[d.z], dvw = g_dotv[d.w];

    float wx = 1.0f / (1.0f + __expf(-(dux + dvx + be)));
    float wy = 1.0f / (1.0f + __expf(-(duy + dvy + be)));
    float wz = 1.0f / (1.0f + __expf(-(duz + dvz + be)));
    float ww = 1.0f / (1.0f + __expf(-(duw + dvw + be)));

    int p;
    p = atomicAdd(&g_cnt[d.x], 1); g_bucket[d.x * CAP + p] = make_int2(s.x, __float_as_int(wx));
    p = atomicAdd(&g_cnt[d.y], 1); g_bucket[d.y * CAP + p] = make_int2(s.y, __float_as_int(wy));
    p = atomicAdd(&g_cnt[d.z], 1); g_bucket[d.z * CAP + p] = make_int2(s.z, __float_as_int(wz));
    p = atomicAdd(&g_cnt[d.w], 1); g_bucket[d.w * CAP + p] = make_int2(s.w, __float_as_int(ww));
}

// ---------------------------------------------------------------------------
// K3: atomic-free aggregate + fused output projection.
// One warp per node; 4 quarter-warps each own every 4th edge.
// Per edge: one broadcast int2 (src, w), two contiguous LDG.128 row loads,
// 4 FFMA2. No gate math in the hot loop.
// ---------------------------------------------------------------------------
__global__ void agg_out_kernel(const float* __restrict__ W_out,
                               const float* __restrict__ b_out,
                               float* __restrict__ out) {
    int lane = threadIdx.x & 31;
    long long n = (long long)(blockIdx.x * blockDim.x + threadIdx.x) >> 5;
    if (n >= N_NODES) return;

    int q = lane >> 3;
    int c = lane & 7;

    int start = (int)n * CAP;
    int cnt   = g_cnt[n];

    // packed accumulators: A[0..1] = feats 4c..4c+3, A[2..3] = feats 32+4c..
    unsigned long long A0 = 0, A1 = 0, A2 = 0, A3 = 0;
    const float4* h4 = (const float4*)g_h;

    int i   = start + q;
    int end = start + cnt;

    // 2-edge unrolled main loop (each quarter-warp strides by 4)
    for (; i + 4 < end; i += 8) {
        int2 eA = g_bucket[i];
        int2 eB = g_bucket[i + 4];
        const float4* rowA = h4 + (long long)eA.x * 16;
        const float4* rowB = h4 + (long long)eB.x * 16;
        float4 vA0 = rowA[c];
        float4 vA1 = rowA[c + 8];
        float4 vB0 = rowB[c];
        float4 vB1 = rowB[c + 8];
        float wA = __int_as_float(eA.y);
        float wB = __int_as_float(eB.y);
        unsigned long long wwA = pack2(wA, wA);
        unsigned long long wwB = pack2(wB, wB);
        fma2(A0, pack2(vA0.x, vA0.y), wwA);
        fma2(A1, pack2(vA0.z, vA0.w), wwA);
        fma2(A2, pack2(vA1.x, vA1.y), wwA);
        fma2(A3, pack2(vA1.z, vA1.w), wwA);
        fma2(A0, pack2(vB0.x, vB0.y), wwB);
        fma2(A1, pack2(vB0.z, vB0.w), wwB);
        fma2(A2, pack2(vB1.x, vB1.y), wwB);
        fma2(A3, pack2(vB1.z, vB1.w), wwB);
    }
    // tail
    for (; i < end; i += 4) {
        int2 e = g_bucket[i];
        const float4* row = h4 + (long long)e.x * 16;
        float4 v0 = row[c];
        float4 v1 = row[c + 8];
        float w = __int_as_float(e.y);
        unsigned long long ww = pack2(w, w);
        fma2(A0, pack2(v0.x, v0.y), ww);
        fma2(A1, pack2(v0.z, v0.w), ww);
        fma2(A2, pack2(v1.x, v1.y), ww);
        fma2(A3, pack2(v1.z, v1.w), ww);
    }

    float4 a0, a1;
    unpack2(A0, a0.x, a0.y); unpack2(A1, a0.z, a0.w);
    unpack2(A2, a1.x, a1.y); unpack2(A3, a1.z, a1.w);

    // reduce across the 4 quarters
#pragma unroll
    for (int off = 8; off <= 16; off <<= 1) {
        a0.x += __shfl_xor_sync(0xffffffffu, a0.x, off);
        a0.y += __shfl_xor_sync(0xffffffffu, a0.y, off);
        a0.z += __shfl_xor_sync(0xffffffffu, a0.z, off);
        a0.w += __shfl_xor_sync(0xffffffffu, a0.w, off);
        a1.x += __shfl_xor_sync(0xffffffffu, a1.x, off);
        a1.y += __shfl_xor_sync(0xffffffffu, a1.y, off);
        a1.z += __shfl_xor_sync(0xffffffffu, a1.z, off);
        a1.w += __shfl_xor_sync(0xffffffffu, a1.w, off);
    }
    if (cnt == 0) {                       // h_new = h when deg==0
        a0 = h4[n * 16 + c];
        a1 = h4[n * 16 + c + 8];
    }

    // out = h_new @ W_out + b_out
    const float4* W4 = (const float4*)W_out;
    float4 wA = W4[2 * c],      wB = W4[2 * c + 1];
    float4 wC = W4[16 + 2 * c], wD = W4[16 + 2 * c + 1];
    float s0 = a0.x * wA.x + a0.y * wA.z + a0.z * wB.x + a0.w * wB.z
             + a1.x * wC.x + a1.y * wC.z + a1.z * wD.x + a1.w * wD.z;
    float s1 = a0.x * wA.y + a0.y * wA.w + a0.z * wB.y + a0.w * wB.w
             + a1.x * wC.y + a1.y * wC.w + a1.z * wD.y + a1.w * wD.w;
#pragma unroll
    for (int off = 1; off <= 4; off <<= 1) {
        s0 += __shfl_xor_sync(0xffffffffu, s0, off);
        s1 += __shfl_xor_sync(0xffffffffu, s1, off);
    }
    if (lane == 0) {
        out[n * 2 + 0] = s0 + b_out[0];
        out[n * 2 + 1] = s1 + b_out[1];
    }
}

// ---------------------------------------------------------------------------
extern "C" void kernel_launch(void* const* d_in, const int* in_sizes, int n_in,
                              void* d_out, int out_size) {
    const float* feat   = (const float*)d_in[0];
    const int*   src    = (const int*)  d_in[1];
    const int*   dst    = (const int*)  d_in[2];
    const float* W_in   = (const float*)d_in[3];
    const float* b_in   = (const float*)d_in[4];
    const float* W_edge = (const float*)d_in[5];
    const float* b_edge = (const float*)d_in[6];
    const float* W_out  = (const float*)d_in[7];
    const float* b_out  = (const float*)d_in[8];
    float* out = (float*)d_out;

    zero_kernel<<<(N_NODES + 255) / 256, 256>>>();
    input_gemm_kernel<<<(N_NODES + 63) / 64, 256>>>(feat, W_in, b_in, W_edge);
    scatter_kernel<<<(N_EDGES / 4 + 255) / 256, 256>>>(src, dst, b_edge);
    agg_out_kernel<<<(int)((N_NODES * 32LL + 255) / 256), 256>>>(W_out, b_out, out);
}